// round 3
// baseline (speedup 1.0000x reference)
#include <cuda_runtime.h>
#include <math.h>

#define LL   9216
#define DI   192
#define DS   16
#define DR   6
#define KK   4
#define XD   38
#define NB   2
#define NSEG 192
#define CH   48       // LL / NSEG
#define HH   96
#define WW   96
#define TLC  128

// ---------------- scratch ----------------
__device__ float g_xi [NB*LL*DI];
__device__ float g_z  [NB*LL*DI];
__device__ float g_xc [NB*LL*DI];
__device__ float g_e1 [NB*KK*LL*DI];   // exp(delta*Ar0), scan order
__device__ float g_du [NB*KK*LL*DI];   // delta*u, scan order
__device__ float g_us [NB*KK*LL*DI];   // u, scan order
__device__ float g_bc [NB*KK*LL*32];
__device__ float g_y  [NB*KK*LL*DI];
__device__ float g_S  [NB*KK*NSEG*DS*DI];
__device__ float g_dsm[NB*KK*NSEG*DI];  // fast: prod(e1) over segment; slow: sum(delta)
__device__ float g_h0 [NB*KK*NSEG*DS*DI];

__device__ __forceinline__ float softplusf_(float x){
    return fmaxf(x, 0.f) + log1pf(expf(-fabsf(x)));
}
__device__ __forceinline__ int pos_of(int k, int i){
    int t = (k >= 2) ? (LL - 1 - i) : i;
    if (k & 1){ int h = t % HH; int w = t / HH; return h*WW + w; }
    return t;
}
__device__ __forceinline__ bool row_fast(const float* arow){
    float a0 = arow[0];
    bool fast = true;
    #pragma unroll
    for (int n = 1; n < DS; n++)
        fast = fast && (fabsf(arow[n] - a0 - logf((float)(n+1))) <= 2e-5f);
    return fast;
}

// ---------------- kernel A: in_proj, 128 outs x 144 px per block ----------------
__global__ void __launch_bounds__(384) kA(const float* __restrict__ x, const float* __restrict__ w){
    extern __shared__ float s[];
    float* sw = s;               // [128][100]
    float* sx = sw + 128*100;    // [144][100]
    int tid = threadIdx.x;
    int bid = blockIdx.x;
    int b   = bid / 192;
    int r   = bid % 192;
    int og  = r / 64;            // 0..2 -> outs og*128..+127
    int l0  = (r % 64) * 144;

    for (int i = tid; i < 128*96; i += 384){
        int o = i/96, e = i%96; sw[o*100 + e] = w[(og*128 + o)*96 + e];
    }
    for (int i = tid; i < 96*144; i += 384){
        int e = i / 144, j = i % 144;
        sx[j*100 + e] = x[(b*96 + e)*LL + l0 + j];
    }
    __syncthreads();

    int ot = tid >> 3 & 31;      // careful: 384 threads -> ot = tid/12? No: use below
    // layout: 384 = 32 (ot) x 12 (pt)
    ot = tid / 12;               // 0..31 -> outs ot*4..+3
    int pt = tid % 12;           // px = pt + 12*j, j<12

    float acc[4][12];
    #pragma unroll
    for (int i = 0; i < 4; i++)
        #pragma unroll
        for (int j = 0; j < 12; j++) acc[i][j] = 0.f;

    for (int e = 0; e < 96; e += 4){
        float4 wv[4];
        #pragma unroll
        for (int i = 0; i < 4; i++) wv[i] = *(const float4*)(sw + (ot*4 + i)*100 + e);
        #pragma unroll
        for (int j = 0; j < 12; j++){
            float4 xv = *(const float4*)(sx + (pt + 12*j)*100 + e);
            #pragma unroll
            for (int i = 0; i < 4; i++){
                acc[i][j] += wv[i].x*xv.x + wv[i].y*xv.y + wv[i].z*xv.z + wv[i].w*xv.w;
            }
        }
    }
    __syncthreads();
    // stage to smem [144][129], then coalesced global write
    float* sbuf = s;
    #pragma unroll
    for (int j = 0; j < 12; j++){
        int px = pt + 12*j;
        #pragma unroll
        for (int i = 0; i < 4; i++) sbuf[px*129 + ot*4 + i] = acc[i][j];
    }
    __syncthreads();
    for (int idx = tid; idx < 144*128; idx += 384){
        int px = idx >> 7, o = idx & 127;
        float v = sbuf[px*129 + o];
        int oo = og*128 + o;
        int base = (b*LL + l0 + px)*DI;
        if (oo < DI) g_xi[base + oo]      = v;
        else         g_z [base + oo - DI] = v;
    }
}

// ---------------- kernel B: depthwise 3x3 conv + SiLU ----------------
__global__ void kB(const float* __restrict__ cw, const float* __restrict__ cb){
    __shared__ float scw[DI*9];
    __shared__ float scb[DI];
    for (int i = threadIdx.x; i < DI*9; i += blockDim.x) scw[i] = cw[i];
    for (int i = threadIdx.x; i < DI;   i += blockDim.x) scb[i] = cb[i];
    __syncthreads();
    int idx = blockIdx.x*blockDim.x + threadIdx.x;
    if (idx >= NB*LL*DI) return;
    int d = idx % DI; int l = (idx/DI) % LL; int b = idx/(DI*LL);
    int h = l / WW, w = l % WW;
    float acc = scb[d];
    #pragma unroll
    for (int ky = 0; ky < 3; ky++){
        int hh = h + ky - 1; if (hh < 0 || hh >= HH) continue;
        #pragma unroll
        for (int kx = 0; kx < 3; kx++){
            int w2 = w + kx - 1; if (w2 < 0 || w2 >= WW) continue;
            acc += scw[d*9 + ky*3 + kx] * g_xi[(b*LL + hh*WW + w2)*DI + d];
        }
    }
    g_xc[idx] = acc * (1.f / (1.f + __expf(-acc)));
}

// ---------------- kernel C1: x_proj + dt proj + scan-stream precompute ----------------
__global__ void __launch_bounds__(320) kC1(const float* __restrict__ xpw, const float* __restrict__ dtw,
                    const float* __restrict__ dtb, const float* __restrict__ A_logs){
    extern __shared__ float s[];
    float* swp = s;                     // [40][192]
    float* sdw = swp + 40*DI;           // [192][6]
    float* sdb = sdw + DI*DR;           // [192]
    float* sa0 = sdb + DI;              // [192] : -exp(A_logs[k,d,0])
    float* sxs = sa0 + DI;              // [128][196]
    float* sxd = sxs + TLC*196;         // [128][40]
    int tid = threadIdx.x;
    int tile   = blockIdx.x;
    int ntile  = LL / TLC;
    int g  = tile / ntile;
    int i0 = (tile % ntile) * TLC;
    int b = g / KK, k = g % KK;

    for (int i = tid; i < 40*DI; i += 320)
        swp[i] = (i < XD*DI) ? xpw[k*XD*DI + i] : 0.f;
    for (int i = tid; i < DI*DR; i += 320) sdw[i] = dtw[k*DI*DR + i];
    for (int i = tid; i < DI;    i += 320){
        sdb[i] = dtb[k*DI + i];
        sa0[i] = -expf(A_logs[(k*DI + i)*DS]);
    }
    for (int i = tid; i < TLC*DI; i += 320){
        int j = i / DI, d = i % DI;
        sxs[j*196 + d] = g_xc[(b*LL + pos_of(k, i0 + j))*DI + d];
    }
    __syncthreads();

    {
        int ot = tid >> 5;
        int pt = tid & 31;
        float acc[4][4];
        #pragma unroll
        for (int i = 0; i < 4; i++)
            #pragma unroll
            for (int j = 0; j < 4; j++) acc[i][j] = 0.f;
        for (int e = 0; e < DI; e += 4){
            float4 xv[4];
            #pragma unroll
            for (int j = 0; j < 4; j++) xv[j] = *(const float4*)(sxs + (pt + 32*j)*196 + e);
            #pragma unroll
            for (int i = 0; i < 4; i++){
                float4 wv = *(const float4*)(swp + (ot*4 + i)*DI + e);
                #pragma unroll
                for (int j = 0; j < 4; j++){
                    acc[i][j] += wv.x*xv[j].x + wv.y*xv[j].y + wv.z*xv[j].z + wv.w*xv[j].w;
                }
            }
        }
        #pragma unroll
        for (int i = 0; i < 4; i++)
            #pragma unroll
            for (int j = 0; j < 4; j++)
                sxd[(pt + 32*j)*40 + ot*4 + i] = acc[i][j];
    }
    __syncthreads();

    for (int o = tid; o < TLC*32; o += 320){
        int j = o >> 5, c = o & 31;
        g_bc[((size_t)g*LL + i0 + j)*32 + c] = sxd[j*40 + 6 + c];
    }
    for (int o = tid; o < TLC*DI; o += 320){
        int j = o / DI, d = o % DI;
        const float* xd = sxd + j*40;
        const float* dw = sdw + d*DR;
        float acc = sdb[d];
        #pragma unroll
        for (int r = 0; r < DR; r++) acc += xd[r]*dw[r];
        float delta = softplusf_(acc);
        float u = sxs[j*196 + d];
        size_t gi = ((size_t)g*LL + i0 + j)*DI + d;
        g_e1[gi] = __expf(delta * sa0[d]);
        g_du[gi] = delta * u;
        g_us[gi] = u;
    }
}

// power set helper: given e1, fills p[0..15] = e1^(n+1), log depth
#define POWER_CHAIN(e1, P) { \
    float e2 = (e1)*(e1); float e4 = e2*e2; float e8 = e4*e4; \
    P[0]=(e1); P[1]=e2; P[2]=e2*(e1); P[3]=e4; P[4]=e4*(e1); P[5]=e4*e2; P[6]=e4*P[2]; \
    P[7]=e8; P[8]=e8*(e1); P[9]=e8*e2; P[10]=e8*P[2]; P[11]=e8*e4; P[12]=e8*P[4]; \
    P[13]=e8*P[5]; P[14]=e8*P[6]; P[15]=e8*e8; }

// ---------------- kernel D1: per-segment partial scan ----------------
__global__ void __launch_bounds__(96) kD1(const float* __restrict__ A_logs){
    __shared__ float sB[CH*DS];
    int blk = blockIdx.x;
    int half = blk & 1;
    int gs  = blk >> 1;
    int g   = gs / NSEG;
    int seg = gs % NSEG;
    int k = g % KK;
    int d = half*96 + threadIdx.x;
    int l0 = seg * CH;

    for (int i = threadIdx.x; i < CH*DS; i += 96){
        int ss = i >> 4, c = i & 15;
        sB[i] = g_bc[((size_t)g*LL + l0 + ss)*32 + c];
    }
    __syncthreads();

    const float* arow = A_logs + (k*DI + d)*DS;
    bool fast = row_fast(arow);
    float h[DS];
    #pragma unroll
    for (int n = 0; n < DS; n++) h[n] = 0.f;

    const float* e1p = g_e1 + ((size_t)g*LL + l0)*DI + d;
    const float* dup = g_du + ((size_t)g*LL + l0)*DI + d;

    if (fast){
        float eprod = 1.f;
        float e1 = e1p[0], du = dup[0];
        for (int s2 = 0; s2 < CH; s2++){
            float ne = 0.f, ndu = 0.f;
            if (s2 + 1 < CH){ ne = e1p[(s2+1)*DI]; ndu = dup[(s2+1)*DI]; }
            float P[DS];
            POWER_CHAIN(e1, P);
            eprod *= e1;
            const float4* Bp4 = (const float4*)(sB + s2*DS);
            float4 b0 = Bp4[0], b1 = Bp4[1], b2 = Bp4[2], b3 = Bp4[3];
            h[0]=P[0]*h[0]+du*b0.x;  h[1]=P[1]*h[1]+du*b0.y;
            h[2]=P[2]*h[2]+du*b0.z;  h[3]=P[3]*h[3]+du*b0.w;
            h[4]=P[4]*h[4]+du*b1.x;  h[5]=P[5]*h[5]+du*b1.y;
            h[6]=P[6]*h[6]+du*b1.z;  h[7]=P[7]*h[7]+du*b1.w;
            h[8]=P[8]*h[8]+du*b2.x;  h[9]=P[9]*h[9]+du*b2.y;
            h[10]=P[10]*h[10]+du*b2.z; h[11]=P[11]*h[11]+du*b2.w;
            h[12]=P[12]*h[12]+du*b3.x; h[13]=P[13]*h[13]+du*b3.y;
            h[14]=P[14]*h[14]+du*b3.z; h[15]=P[15]*h[15]+du*b3.w;
            e1 = ne; du = ndu;
        }
        g_dsm[((size_t)g*NSEG + seg)*DI + d] = eprod;
    } else {
        float Ar[DS];
        #pragma unroll
        for (int n = 0; n < DS; n++) Ar[n] = -expf(arow[n]);
        float inv0 = 1.f / Ar[0];
        float dsum = 0.f;
        for (int s2 = 0; s2 < CH; s2++){
            float e1 = e1p[s2*DI];
            float du = dup[s2*DI];
            float delta = __logf(e1) * inv0;
            dsum += delta;
            const float* Bp = sB + s2*DS;
            #pragma unroll
            for (int n = 0; n < DS; n++){
                float e = __expf(delta*Ar[n]);
                h[n] = e*h[n] + du*Bp[n];
            }
        }
        g_dsm[((size_t)g*NSEG + seg)*DI + d] = dsum;
    }
    size_t sbase = (((size_t)g*NSEG + seg)*DS)*DI + d;
    #pragma unroll
    for (int n = 0; n < DS; n++) g_S[sbase + n*DI] = h[n];
}

// ---------------- kernel D2: stitch segment boundaries ----------------
__global__ void kD2(const float* __restrict__ A_logs){
    int t = blockIdx.x*blockDim.x + threadIdx.x;
    if (t >= NB*KK*DS*DI) return;
    int d = t % DI; int n = (t/DI) % DS; int g = t/(DI*DS);
    int k = g % KK;
    const float* arow = A_logs + (k*DI + d)*DS;
    bool fast = row_fast(arow);
    float h = 0.f;
    size_t base0 = (size_t)g*NSEG;
    float dsm = g_dsm[base0*DI + d];
    float Sv  = g_S[(base0*DS + n)*DI + d];
    if (fast){
        int m = n + 1;
        for (int seg = 0; seg < NSEG; seg++){
            size_t base = base0 + seg;
            float ndsm = 0.f, nS = 0.f;
            if (seg + 1 < NSEG){
                ndsm = g_dsm[(base+1)*DI + d];
                nS   = g_S[((base+1)*DS + n)*DI + d];
            }
            g_h0[(base*DS + n)*DI + d] = h;
            // P = dsm^(n+1)
            float p = 1.f, bse = dsm; int mm = m;
            #pragma unroll
            for (int it = 0; it < 5; it++){
                if (mm & 1) p *= bse;
                bse *= bse; mm >>= 1;
            }
            h = p*h + Sv;
            dsm = ndsm; Sv = nS;
        }
    } else {
        float An = -expf(arow[n]);
        for (int seg = 0; seg < NSEG; seg++){
            size_t base = base0 + seg;
            float ndsm = 0.f, nS = 0.f;
            if (seg + 1 < NSEG){
                ndsm = g_dsm[(base+1)*DI + d];
                nS   = g_S[((base+1)*DS + n)*DI + d];
            }
            g_h0[(base*DS + n)*DI + d] = h;
            h = __expf(An*dsm)*h + Sv;
            dsm = ndsm; Sv = nS;
        }
    }
}

// ---------------- kernel D3: full scan, emit y ----------------
__global__ void __launch_bounds__(96) kD3(const float* __restrict__ A_logs,
                                          const float* __restrict__ Dsv){
    __shared__ float sBC[CH*32];
    int blk = blockIdx.x;
    int half = blk & 1;
    int gs  = blk >> 1;
    int g   = gs / NSEG;
    int seg = gs % NSEG;
    int k = g % KK;
    int d = half*96 + threadIdx.x;
    int l0 = seg * CH;

    {
        const float4* src = (const float4*)(g_bc + ((size_t)g*LL + l0)*32);
        float4* dst = (float4*)sBC;
        for (int i = threadIdx.x; i < CH*8; i += 96) dst[i] = src[i];
    }
    __syncthreads();

    const float* arow = A_logs + (k*DI + d)*DS;
    bool fast = row_fast(arow);

    float h[DS];
    size_t hbase = (((size_t)g*NSEG + seg)*DS)*DI + d;
    #pragma unroll
    for (int n = 0; n < DS; n++) h[n] = g_h0[hbase + n*DI];
    float Dval = Dsv[k*DI + d];

    const float* e1p = g_e1 + ((size_t)g*LL + l0)*DI + d;
    const float* dup = g_du + ((size_t)g*LL + l0)*DI + d;
    const float* usp = g_us + ((size_t)g*LL + l0)*DI + d;
    float* yptr = g_y + ((size_t)g*LL + l0)*DI + d;

    if (fast){
        float e1 = e1p[0], du = dup[0], u = usp[0];
        for (int s2 = 0; s2 < CH; s2++){
            float ne = 0.f, ndu = 0.f, nu = 0.f;
            if (s2 + 1 < CH){
                ne = e1p[(s2+1)*DI]; ndu = dup[(s2+1)*DI]; nu = usp[(s2+1)*DI];
            }
            float P[DS];
            POWER_CHAIN(e1, P);
            const float4* P4 = (const float4*)(sBC + s2*32);
            float4 b0 = P4[0], b1 = P4[1], b2 = P4[2], b3 = P4[3];
            float4 c0 = P4[4], c1 = P4[5], c2 = P4[6], c3 = P4[7];
            float y = 0.f;
            h[0]=P[0]*h[0]+du*b0.x;  y+=h[0]*c0.x;
            h[1]=P[1]*h[1]+du*b0.y;  y+=h[1]*c0.y;
            h[2]=P[2]*h[2]+du*b0.z;  y+=h[2]*c0.z;
            h[3]=P[3]*h[3]+du*b0.w;  y+=h[3]*c0.w;
            h[4]=P[4]*h[4]+du*b1.x;  y+=h[4]*c1.x;
            h[5]=P[5]*h[5]+du*b1.y;  y+=h[5]*c1.y;
            h[6]=P[6]*h[6]+du*b1.z;  y+=h[6]*c1.z;
            h[7]=P[7]*h[7]+du*b1.w;  y+=h[7]*c1.w;
            h[8]=P[8]*h[8]+du*b2.x;  y+=h[8]*c2.x;
            h[9]=P[9]*h[9]+du*b2.y;  y+=h[9]*c2.y;
            h[10]=P[10]*h[10]+du*b2.z; y+=h[10]*c2.z;
            h[11]=P[11]*h[11]+du*b2.w; y+=h[11]*c2.w;
            h[12]=P[12]*h[12]+du*b3.x; y+=h[12]*c3.x;
            h[13]=P[13]*h[13]+du*b3.y; y+=h[13]*c3.y;
            h[14]=P[14]*h[14]+du*b3.z; y+=h[14]*c3.z;
            h[15]=P[15]*h[15]+du*b3.w; y+=h[15]*c3.w;
            yptr[s2*DI] = y + Dval*u;
            e1 = ne; du = ndu; u = nu;
        }
    } else {
        float Ar[DS];
        #pragma unroll
        for (int n = 0; n < DS; n++) Ar[n] = -expf(arow[n]);
        float inv0 = 1.f / Ar[0];
        for (int s2 = 0; s2 < CH; s2++){
            float e1v = e1p[s2*DI];
            float du  = dup[s2*DI];
            float u   = usp[s2*DI];
            float delta = __logf(e1v) * inv0;
            const float* Bp = sBC + s2*32;
            const float* Cp = Bp + 16;
            float y = 0.f;
            #pragma unroll
            for (int n = 0; n < DS; n++){
                float e = __expf(delta*Ar[n]);
                h[n] = e*h[n] + du*Bp[n];
                y += h[n]*Cp[n];
            }
            yptr[s2*DI] = y + Dval*u;
        }
    }
}

// ---------------- kernel E: merge + LN + gate + out_proj + residual ----------------
__global__ void __launch_bounds__(256) kE(const float* __restrict__ opw,
                                          const float* __restrict__ lng,
                                          const float* __restrict__ lnb,
                                          const float* __restrict__ x,
                                          float* __restrict__ out){
    extern __shared__ float s[];
    float* sw  = s;              // [96][196]
    float* syo = sw + 96*196;    // [64][196]
    float* slg = syo + 64*196;
    float* slb = slg + DI;

    int tid = threadIdx.x;
    int b  = blockIdx.x / (LL/64);
    int p0 = (blockIdx.x % (LL/64)) * 64;

    for (int i = tid; i < 96*DI; i += 256){
        int c = i/DI, e = i%DI; sw[c*196 + e] = opw[i];
    }
    for (int i = tid; i < DI; i += 256){ slg[i] = lng[i]; slb[i] = lnb[i]; }
    __syncthreads();

    int lane = tid & 31, wrp = tid >> 5;

    for (int jj = 0; jj < 8; jj++){
        int j = wrp*8 + jj;
        int p = p0 + j;
        int ph = p / WW, pw = p % WW;
        int i1 = pw*HH + ph;
        float val[6];
        #pragma unroll
        for (int i = 0; i < 6; i++){
            int d = lane + 32*i;
            val[i] = g_y[(((size_t)(b*KK + 0))*LL + p)*DI + d]
                   + g_y[(((size_t)(b*KK + 2))*LL + (LL-1-p))*DI + d]
                   + g_y[(((size_t)(b*KK + 1))*LL + i1)*DI + d]
                   + g_y[(((size_t)(b*KK + 3))*LL + (LL-1-i1))*DI + d];
        }
        float s1 = 0.f, s2 = 0.f;
        #pragma unroll
        for (int i = 0; i < 6; i++){ s1 += val[i]; s2 += val[i]*val[i]; }
        #pragma unroll
        for (int off = 16; off; off >>= 1){
            s1 += __shfl_xor_sync(0xffffffffu, s1, off);
            s2 += __shfl_xor_sync(0xffffffffu, s2, off);
        }
        float mu  = s1 * (1.f/192.f);
        float var = s2 * (1.f/192.f) - mu*mu;
        float inv = rsqrtf(var + 1e-5f);
        #pragma unroll
        for (int i = 0; i < 6; i++){
            int d = lane + 32*i;
            float yo = (val[i] - mu)*inv*slg[d] + slb[d];
            float zv = g_z[((size_t)b*LL + p)*DI + d];
            yo *= zv * (1.f / (1.f + __expf(-zv)));
            syo[j*196 + d] = yo;
        }
    }
    __syncthreads();

    int ct = tid >> 4;
    int pt = tid & 15;
    float acc[6][4];
    #pragma unroll
    for (int i = 0; i < 6; i++)
        #pragma unroll
        for (int j = 0; j < 4; j++) acc[i][j] = 0.f;
    for (int e = 0; e < DI; e += 4){
        float4 xv[4];
        #pragma unroll
        for (int j = 0; j < 4; j++) xv[j] = *(const float4*)(syo + (pt + 16*j)*196 + e);
        #pragma unroll
        for (int i = 0; i < 6; i++){
            float4 wv = *(const float4*)(sw + (ct*6 + i)*196 + e);
            #pragma unroll
            for (int j = 0; j < 4; j++){
                acc[i][j] += wv.x*xv[j].x + wv.y*xv[j].y + wv.z*xv[j].z + wv.w*xv[j].w;
            }
        }
    }
    __syncthreads();
    #pragma unroll
    for (int i = 0; i < 6; i++)
        #pragma unroll
        for (int j = 0; j < 4; j++)
            syo[(ct*6 + i)*64 + pt + 16*j] = acc[i][j];
    __syncthreads();
    for (int idx = tid; idx < 96*64; idx += 256){
        int c = idx >> 6, jx = idx & 63;
        size_t go = ((size_t)b*96 + c)*LL + p0 + jx;
        out[go] = syo[idx] + x[go];
    }
}

// ---------------- launch ----------------
extern "C" void kernel_launch(void* const* d_in, const int* in_sizes, int n_in,
                              void* d_out, int out_size){
    const float* x    = (const float*)d_in[0];
    const float* ipw  = (const float*)d_in[1];
    const float* cw   = (const float*)d_in[2];
    const float* cb   = (const float*)d_in[3];
    const float* xpw  = (const float*)d_in[4];
    const float* dtw  = (const float*)d_in[5];
    const float* dtb  = (const float*)d_in[6];
    const float* alog = (const float*)d_in[7];
    const float* Dsv  = (const float*)d_in[8];
    const float* lng  = (const float*)d_in[9];
    const float* lnb  = (const float*)d_in[10];
    const float* opw  = (const float*)d_in[11];
    float* out = (float*)d_out;

    int smA = (128*100 + 144*100) * 4;                        // 108800
    int smC = (40*DI + DI*DR + DI + DI + TLC*196 + TLC*40) * 4;
    int smE = (96*196 + 64*196 + DI + DI) * 4;
    cudaFuncSetAttribute(kA,  cudaFuncAttributeMaxDynamicSharedMemorySize, smA);
    cudaFuncSetAttribute(kC1, cudaFuncAttributeMaxDynamicSharedMemorySize, smC);
    cudaFuncSetAttribute(kE,  cudaFuncAttributeMaxDynamicSharedMemorySize, smE);

    kA<<<NB*3*64, 384, smA>>>(x, ipw);
    kB<<<(NB*LL*DI + 255)/256, 256>>>(cw, cb);
    kC1<<<NB*KK*(LL/TLC), 320, smC>>>(xpw, dtw, dtb, alog);
    kD1<<<NB*KK*NSEG*2, 96>>>(alog);
    kD2<<<(NB*KK*DS*DI + 255)/256, 256>>>(alog);
    kD3<<<NB*KK*NSEG*2, 96>>>(alog, Dsv);
    kE<<<NB*(LL/64), 256, smE>>>(opw, lng, lnb, x, out);
}

// round 4
// speedup vs baseline: 1.3332x; 1.3332x over previous
#include <cuda_runtime.h>
#include <math.h>

#define LL   9216
#define DI   192
#define DS   16
#define DR   6
#define KK   4
#define XD   38
#define NB   2
#define NSEG 192
#define CH   48       // LL / NSEG ; 48 divides 96 -> affine gather per segment
#define HH   96
#define WW   96
#define TLC  128

// ---------------- scratch ----------------
__device__ float g_xi   [NB*LL*DI];
__device__ float g_z    [NB*LL*DI];
__device__ float g_xc   [NB*LL*DI];
__device__ float g_delta[NB*KK*LL*DI];
__device__ float g_bc   [NB*KK*LL*32];
__device__ float g_y    [NB*KK*LL*DI];
__device__ float g_S    [NB*KK*NSEG*DS*DI];
__device__ float g_dsm  [NB*KK*NSEG*DI];
__device__ float g_h0   [NB*KK*NSEG*DS*DI];

__device__ __forceinline__ float softplusf_(float x){
    return fmaxf(x, 0.f) + log1pf(expf(-fabsf(x)));
}
__device__ __forceinline__ int pos_of(int k, int i){
    int t = (k >= 2) ? (LL - 1 - i) : i;
    if (k & 1){ int h = t % HH; int w = t / HH; return h*WW + w; }
    return t;
}
__device__ __forceinline__ bool row_fast(const float* arow){
    float a0 = arow[0];
    bool fast = true;
    #pragma unroll
    for (int n = 1; n < DS; n++)
        fast = fast && (fabsf(arow[n] - a0 - logf((float)(n+1))) <= 2e-5f);
    return fast;
}
// pixel stride (in pixels) per scan step for direction k, valid within a 48-step segment
__device__ __forceinline__ int pstride_of(int k){
    return (k==0) ? 1 : (k==1) ? WW : (k==2) ? -1 : -WW;
}

// ---------------- kernel A: in_proj, 128 outs x 144 px per block ----------------
__global__ void __launch_bounds__(384) kA(const float* __restrict__ x, const float* __restrict__ w){
    extern __shared__ float s[];
    float* sw = s;               // [128][100]
    float* sx = sw + 128*100;    // [144][100]
    int tid = threadIdx.x;
    int bid = blockIdx.x;
    int b   = bid / 192;
    int r   = bid % 192;
    int og  = r / 64;            // 0..2 -> outs og*128..+127
    int l0  = (r % 64) * 144;

    for (int i = tid; i < 128*96; i += 384){
        int o = i/96, e = i%96; sw[o*100 + e] = w[(og*128 + o)*96 + e];
    }
    for (int i = tid; i < 96*144; i += 384){
        int e = i / 144, j = i % 144;
        sx[j*100 + e] = x[(b*96 + e)*LL + l0 + j];
    }
    __syncthreads();

    int ot = tid / 12;           // 0..31 -> outs ot*4..+3
    int pt = tid % 12;           // px = pt + 12*j, j<12

    float acc[4][12];
    #pragma unroll
    for (int i = 0; i < 4; i++)
        #pragma unroll
        for (int j = 0; j < 12; j++) acc[i][j] = 0.f;

    for (int e = 0; e < 96; e += 4){
        float4 wv[4];
        #pragma unroll
        for (int i = 0; i < 4; i++) wv[i] = *(const float4*)(sw + (ot*4 + i)*100 + e);
        #pragma unroll
        for (int j = 0; j < 12; j++){
            float4 xv = *(const float4*)(sx + (pt + 12*j)*100 + e);
            #pragma unroll
            for (int i = 0; i < 4; i++){
                acc[i][j] += wv[i].x*xv.x + wv[i].y*xv.y + wv[i].z*xv.z + wv[i].w*xv.w;
            }
        }
    }
    __syncthreads();
    float* sbuf = s;   // [144][129]
    #pragma unroll
    for (int j = 0; j < 12; j++){
        int px = pt + 12*j;
        #pragma unroll
        for (int i = 0; i < 4; i++) sbuf[px*129 + ot*4 + i] = acc[i][j];
    }
    __syncthreads();
    for (int idx = tid; idx < 144*128; idx += 384){
        int px = idx >> 7, o = idx & 127;
        float v = sbuf[px*129 + o];
        int oo = og*128 + o;
        int base = (b*LL + l0 + px)*DI;
        if (oo < DI) g_xi[base + oo]      = v;
        else         g_z [base + oo - DI] = v;
    }
}

// ---------------- kernel B: depthwise 3x3 conv + SiLU, 2px x 2ch per thread ----------------
__global__ void __launch_bounds__(256) kB(const float* __restrict__ cw, const float* __restrict__ cb){
    __shared__ float scwT[9*DI];   // transposed: [tap][d]
    __shared__ float scb[DI];
    for (int i = threadIdx.x; i < DI*9; i += 256){
        int d = i/9, t = i%9; scwT[t*DI + d] = cw[i];
    }
    for (int i = threadIdx.x; i < DI; i += 256) scb[i] = cb[i];
    __syncthreads();

    int idx = blockIdx.x*256 + threadIdx.x;
    if (idx >= NB*(LL/2)*(DI/2)) return;
    int d2 = idx % 96;           // channel pair: d = 2*d2, 2*d2+1
    int t  = idx / 96;
    int wp = t % 48;             // pixel pair: w = 2*wp, 2*wp+1
    int h  = (t / 48) % 96;
    int b  = t / (48*96);
    int d  = 2*d2;

    float a0x = scb[d], a0y = scb[d+1];
    float a1x = a0x,    a1y = a0y;
    int wl = 2*wp - 1;
    bool hasL = (wl >= 0), hasR = (2*wp + 2 < WW);

    #pragma unroll
    for (int ky = 0; ky < 3; ky++){
        int hh = h + ky - 1; if (hh < 0 || hh >= HH) continue;
        const float* row = g_xi + ((size_t)b*LL + hh*WW)*DI + d;
        float2 v0 = hasL ? *(const float2*)(row + wl*DI)        : make_float2(0.f,0.f);
        float2 v1 =        *(const float2*)(row + (2*wp)*DI);
        float2 v2 =        *(const float2*)(row + (2*wp+1)*DI);
        float2 v3 = hasR ? *(const float2*)(row + (2*wp+2)*DI)  : make_float2(0.f,0.f);
        float2 w0 = *(const float2*)(scwT + (ky*3+0)*DI + d);
        float2 w1 = *(const float2*)(scwT + (ky*3+1)*DI + d);
        float2 w2 = *(const float2*)(scwT + (ky*3+2)*DI + d);
        a0x += w0.x*v0.x + w1.x*v1.x + w2.x*v2.x;
        a0y += w0.y*v0.y + w1.y*v1.y + w2.y*v2.y;
        a1x += w0.x*v1.x + w1.x*v2.x + w2.x*v3.x;
        a1y += w0.y*v1.y + w1.y*v2.y + w2.y*v3.y;
    }
    float2 o0, o1;
    o0.x = a0x * (1.f/(1.f+__expf(-a0x)));
    o0.y = a0y * (1.f/(1.f+__expf(-a0y)));
    o1.x = a1x * (1.f/(1.f+__expf(-a1x)));
    o1.y = a1y * (1.f/(1.f+__expf(-a1y)));
    float* orow = g_xc + ((size_t)b*LL + h*WW)*DI + d;
    *(float2*)(orow + (2*wp)*DI)   = o0;
    *(float2*)(orow + (2*wp+1)*DI) = o1;
}

// ---------------- kernel C1: x_proj + dt proj + softplus ----------------
__global__ void __launch_bounds__(320) kC1(const float* __restrict__ xpw, const float* __restrict__ dtw,
                    const float* __restrict__ dtb){
    extern __shared__ float s[];
    float* swp = s;                     // [40][192]
    float* sdw = swp + 40*DI;           // [192][6]
    float* sdb = sdw + DI*DR;           // [192]
    float* sxs = sdb + DI;              // [128][196]
    float* sxd = sxs + TLC*196;         // [128][40]
    int tid = threadIdx.x;
    int tile   = blockIdx.x;
    int ntile  = LL / TLC;
    int g  = tile / ntile;
    int i0 = (tile % ntile) * TLC;
    int b = g / KK, k = g % KK;

    for (int i = tid; i < 40*DI; i += 320)
        swp[i] = (i < XD*DI) ? xpw[k*XD*DI + i] : 0.f;
    for (int i = tid; i < DI*DR; i += 320) sdw[i] = dtw[k*DI*DR + i];
    for (int i = tid; i < DI;    i += 320) sdb[i] = dtb[k*DI + i];
    for (int i = tid; i < TLC*DI; i += 320){
        int j = i / DI, d = i % DI;
        sxs[j*196 + d] = g_xc[(b*LL + pos_of(k, i0 + j))*DI + d];
    }
    __syncthreads();

    {
        int ot = tid >> 5;
        int pt = tid & 31;
        float acc[4][4];
        #pragma unroll
        for (int i = 0; i < 4; i++)
            #pragma unroll
            for (int j = 0; j < 4; j++) acc[i][j] = 0.f;
        for (int e = 0; e < DI; e += 4){
            float4 xv[4];
            #pragma unroll
            for (int j = 0; j < 4; j++) xv[j] = *(const float4*)(sxs + (pt + 32*j)*196 + e);
            #pragma unroll
            for (int i = 0; i < 4; i++){
                float4 wv = *(const float4*)(swp + (ot*4 + i)*DI + e);
                #pragma unroll
                for (int j = 0; j < 4; j++){
                    acc[i][j] += wv.x*xv[j].x + wv.y*xv[j].y + wv.z*xv[j].z + wv.w*xv[j].w;
                }
            }
        }
        #pragma unroll
        for (int i = 0; i < 4; i++)
            #pragma unroll
            for (int j = 0; j < 4; j++)
                sxd[(pt + 32*j)*40 + ot*4 + i] = acc[i][j];
    }
    __syncthreads();

    for (int o = tid; o < TLC*32; o += 320){
        int j = o >> 5, c = o & 31;
        g_bc[((size_t)g*LL + i0 + j)*32 + c] = sxd[j*40 + 6 + c];
    }
    for (int o = tid; o < TLC*DI; o += 320){
        int j = o / DI, d = o % DI;
        const float* xd = sxd + j*40;
        const float* dw = sdw + d*DR;
        float acc = sdb[d];
        #pragma unroll
        for (int r = 0; r < DR; r++) acc += xd[r]*dw[r];
        g_delta[((size_t)g*LL + i0 + j)*DI + d] = softplusf_(acc);
    }
}

// scan step body (fast path): grouped power chain, depth 4
#define STEP_BODY_D1(s2, delta, u) { \
    dsum += (delta); \
    float du = (delta)*(u); \
    float e1 = __expf((delta)*Ar0); \
    float e2 = e1*e1, e4 = e2*e2, e8 = e4*e4, e12 = e8*e4; \
    const float4* Bp4 = (const float4*)(sB + (s2)*DS); \
    float4 B0=Bp4[0],B1=Bp4[1],B2=Bp4[2],B3=Bp4[3]; \
    float aq = e1; \
    h[0]=aq*h[0]+du*B0.x; aq*=e1; h[1]=aq*h[1]+du*B0.y; aq*=e1; h[2]=aq*h[2]+du*B0.z; aq*=e1; h[3]=aq*h[3]+du*B0.w; \
    float bq = e4*e1; \
    h[4]=bq*h[4]+du*B1.x; bq*=e1; h[5]=bq*h[5]+du*B1.y; bq*=e1; h[6]=bq*h[6]+du*B1.z; bq*=e1; h[7]=bq*h[7]+du*B1.w; \
    float cq = e8*e1; \
    h[8]=cq*h[8]+du*B2.x; cq*=e1; h[9]=cq*h[9]+du*B2.y; cq*=e1; h[10]=cq*h[10]+du*B2.z; cq*=e1; h[11]=cq*h[11]+du*B2.w; \
    float dq = e12*e1; \
    h[12]=dq*h[12]+du*B3.x; dq*=e1; h[13]=dq*h[13]+du*B3.y; dq*=e1; h[14]=dq*h[14]+du*B3.z; dq*=e1; h[15]=dq*h[15]+du*B3.w; \
}

// ---------------- kernel D1: per-segment partial scan ----------------
__global__ void __launch_bounds__(192) kD1(const float* __restrict__ A_logs){
    __shared__ float sB[CH*DS];
    int g   = blockIdx.x / NSEG;
    int seg = blockIdx.x % NSEG;
    int b = g / KK, k = g % KK;
    int d = threadIdx.x;
    int l0 = seg * CH;

    for (int i = threadIdx.x; i < CH*DS; i += 192){
        int ss = i >> 4, c = i & 15;
        sB[i] = g_bc[((size_t)g*LL + l0 + ss)*32 + c];
    }
    __syncthreads();

    const float* arow = A_logs + (k*DI + d)*DS;
    bool fast = row_fast(arow);
    float Ar0 = -expf(arow[0]);

    float h[DS];
    #pragma unroll
    for (int n = 0; n < DS; n++) h[n] = 0.f;
    float dsum = 0.f;

    int p0   = pos_of(k, l0);
    int pstr = pstride_of(k) * DI;
    const float* dptr = g_delta + ((size_t)g*LL + l0)*DI + d;
    const float* uptr = g_xc + ((size_t)b*LL + p0)*DI + d;

    if (fast){
        for (int c0 = 0; c0 < CH; c0 += 4){
            float dl[4], uu[4];
            #pragma unroll
            for (int j = 0; j < 4; j++){
                dl[j] = dptr[(c0+j)*DI];
                uu[j] = uptr[(c0+j)*pstr];
            }
            #pragma unroll
            for (int j = 0; j < 4; j++){
                STEP_BODY_D1(c0+j, dl[j], uu[j]);
            }
        }
    } else {
        float Ar[DS];
        #pragma unroll
        for (int n = 0; n < DS; n++) Ar[n] = -expf(arow[n]);
        for (int s2 = 0; s2 < CH; s2++){
            float delta = dptr[s2*DI];
            float u = uptr[s2*pstr];
            dsum += delta;
            float du = delta*u;
            const float* Bp = sB + s2*DS;
            #pragma unroll
            for (int n = 0; n < DS; n++){
                float e = __expf(delta*Ar[n]);
                h[n] = e*h[n] + du*Bp[n];
            }
        }
    }
    size_t sbase = (((size_t)g*NSEG + seg)*DS)*DI + d;
    #pragma unroll
    for (int n = 0; n < DS; n++) g_S[sbase + n*DI] = h[n];
    g_dsm[((size_t)g*NSEG + seg)*DI + d] = dsum;
}

// ---------------- kernel D2: stitch segment boundaries ----------------
__global__ void kD2(const float* __restrict__ A_logs){
    int t = blockIdx.x*blockDim.x + threadIdx.x;
    if (t >= NB*KK*DS*DI) return;
    int d = t % DI; int n = (t/DI) % DS; int g = t/(DI*DS);
    int k = g % KK;
    float An = -expf(A_logs[(k*DI + d)*DS + n]);
    float h = 0.f;
    size_t base0 = (size_t)g*NSEG;
    float dsm = g_dsm[base0*DI + d];
    float Sv  = g_S[(base0*DS + n)*DI + d];
    for (int seg = 0; seg < NSEG; seg++){
        size_t base = base0 + seg;
        float ndsm = 0.f, nS = 0.f;
        if (seg + 1 < NSEG){
            ndsm = g_dsm[(base+1)*DI + d];
            nS   = g_S[((base+1)*DS + n)*DI + d];
        }
        g_h0[(base*DS + n)*DI + d] = h;
        h = __expf(An*dsm)*h + Sv;
        dsm = ndsm; Sv = nS;
    }
}

#define STEP_BODY_D3(s2, delta, u) { \
    float du = (delta)*(u); \
    float e1 = __expf((delta)*Ar0); \
    float e2 = e1*e1, e4 = e2*e2, e8 = e4*e4, e12 = e8*e4; \
    const float4* P4 = (const float4*)(sBC + (s2)*32); \
    float4 B0=P4[0],B1=P4[1],B2=P4[2],B3=P4[3]; \
    float4 C0=P4[4],C1=P4[5],C2=P4[6],C3=P4[7]; \
    float y = 0.f; \
    float aq = e1; \
    h[0]=aq*h[0]+du*B0.x; y+=h[0]*C0.x; aq*=e1; h[1]=aq*h[1]+du*B0.y; y+=h[1]*C0.y; aq*=e1; \
    h[2]=aq*h[2]+du*B0.z; y+=h[2]*C0.z; aq*=e1; h[3]=aq*h[3]+du*B0.w; y+=h[3]*C0.w; \
    float bq = e4*e1; \
    h[4]=bq*h[4]+du*B1.x; y+=h[4]*C1.x; bq*=e1; h[5]=bq*h[5]+du*B1.y; y+=h[5]*C1.y; bq*=e1; \
    h[6]=bq*h[6]+du*B1.z; y+=h[6]*C1.z; bq*=e1; h[7]=bq*h[7]+du*B1.w; y+=h[7]*C1.w; \
    float cq = e8*e1; \
    h[8]=cq*h[8]+du*B2.x; y+=h[8]*C2.x; cq*=e1; h[9]=cq*h[9]+du*B2.y; y+=h[9]*C2.y; cq*=e1; \
    h[10]=cq*h[10]+du*B2.z; y+=h[10]*C2.z; cq*=e1; h[11]=cq*h[11]+du*B2.w; y+=h[11]*C2.w; \
    float dq = e12*e1; \
    h[12]=dq*h[12]+du*B3.x; y+=h[12]*C3.x; dq*=e1; h[13]=dq*h[13]+du*B3.y; y+=h[13]*C3.y; dq*=e1; \
    h[14]=dq*h[14]+du*B3.z; y+=h[14]*C3.z; dq*=e1; h[15]=dq*h[15]+du*B3.w; y+=h[15]*C3.w; \
    yptr[(s2)*DI] = y + Dval*(u); \
}

// ---------------- kernel D3: full scan, emit y ----------------
__global__ void __launch_bounds__(192) kD3(const float* __restrict__ A_logs,
                                           const float* __restrict__ Dsv){
    __shared__ float sBC[CH*32];
    int g   = blockIdx.x / NSEG;
    int seg = blockIdx.x % NSEG;
    int b = g / KK, k = g % KK;
    int d = threadIdx.x;
    int l0 = seg * CH;

    {
        const float4* src = (const float4*)(g_bc + ((size_t)g*LL + l0)*32);
        float4* dst = (float4*)sBC;
        for (int i = threadIdx.x; i < CH*8; i += 192) dst[i] = src[i];
    }
    __syncthreads();

    const float* arow = A_logs + (k*DI + d)*DS;
    bool fast = row_fast(arow);
    float Ar0 = -expf(arow[0]);

    float h[DS];
    size_t hbase = (((size_t)g*NSEG + seg)*DS)*DI + d;
    #pragma unroll
    for (int n = 0; n < DS; n++) h[n] = g_h0[hbase + n*DI];
    float Dval = Dsv[k*DI + d];

    int p0   = pos_of(k, l0);
    int pstr = pstride_of(k) * DI;
    const float* dptr = g_delta + ((size_t)g*LL + l0)*DI + d;
    const float* uptr = g_xc + ((size_t)b*LL + p0)*DI + d;
    float* yptr = g_y + ((size_t)g*LL + l0)*DI + d;

    if (fast){
        for (int c0 = 0; c0 < CH; c0 += 4){
            float dl[4], uu[4];
            #pragma unroll
            for (int j = 0; j < 4; j++){
                dl[j] = dptr[(c0+j)*DI];
                uu[j] = uptr[(c0+j)*pstr];
            }
            #pragma unroll
            for (int j = 0; j < 4; j++){
                STEP_BODY_D3(c0+j, dl[j], uu[j]);
            }
        }
    } else {
        float Ar[DS];
        #pragma unroll
        for (int n = 0; n < DS; n++) Ar[n] = -expf(arow[n]);
        for (int s2 = 0; s2 < CH; s2++){
            float delta = dptr[s2*DI];
            float u = uptr[s2*pstr];
            float du = delta*u;
            const float* Bp = sBC + s2*32;
            const float* Cp = Bp + 16;
            float y = 0.f;
            #pragma unroll
            for (int n = 0; n < DS; n++){
                float e = __expf(delta*Ar[n]);
                h[n] = e*h[n] + du*Bp[n];
                y += h[n]*Cp[n];
            }
            yptr[s2*DI] = y + Dval*u;
        }
    }
}

// ---------------- kernel E: merge + LN + gate + out_proj + residual ----------------
__global__ void __launch_bounds__(256) kE(const float* __restrict__ opw,
                                          const float* __restrict__ lng,
                                          const float* __restrict__ lnb,
                                          const float* __restrict__ x,
                                          float* __restrict__ out){
    extern __shared__ float s[];
    float* sw  = s;              // [96][196]
    float* syo = sw + 96*196;    // [64][196]
    float* slg = syo + 64*196;
    float* slb = slg + DI;

    int tid = threadIdx.x;
    int b  = blockIdx.x / (LL/64);
    int p0 = (blockIdx.x % (LL/64)) * 64;

    for (int i = tid; i < 96*DI; i += 256){
        int c = i/DI, e = i%DI; sw[c*196 + e] = opw[i];
    }
    for (int i = tid; i < DI; i += 256){ slg[i] = lng[i]; slb[i] = lnb[i]; }
    __syncthreads();

    int lane = tid & 31, wrp = tid >> 5;

    for (int jj = 0; jj < 8; jj++){
        int j = wrp*8 + jj;
        int p = p0 + j;
        int ph = p / WW, pw = p % WW;
        int i1 = pw*HH + ph;
        float val[6];
        #pragma unroll
        for (int i = 0; i < 6; i++){
            int d = lane + 32*i;
            val[i] = g_y[(((size_t)(b*KK + 0))*LL + p)*DI + d]
                   + g_y[(((size_t)(b*KK + 2))*LL + (LL-1-p))*DI + d]
                   + g_y[(((size_t)(b*KK + 1))*LL + i1)*DI + d]
                   + g_y[(((size_t)(b*KK + 3))*LL + (LL-1-i1))*DI + d];
        }
        float s1 = 0.f, s2 = 0.f;
        #pragma unroll
        for (int i = 0; i < 6; i++){ s1 += val[i]; s2 += val[i]*val[i]; }
        #pragma unroll
        for (int off = 16; off; off >>= 1){
            s1 += __shfl_xor_sync(0xffffffffu, s1, off);
            s2 += __shfl_xor_sync(0xffffffffu, s2, off);
        }
        float mu  = s1 * (1.f/192.f);
        float var = s2 * (1.f/192.f) - mu*mu;
        float inv = rsqrtf(var + 1e-5f);
        #pragma unroll
        for (int i = 0; i < 6; i++){
            int d = lane + 32*i;
            float yo = (val[i] - mu)*inv*slg[d] + slb[d];
            float zv = g_z[((size_t)b*LL + p)*DI + d];
            yo *= zv * (1.f / (1.f + __expf(-zv)));
            syo[j*196 + d] = yo;
        }
    }
    __syncthreads();

    int ct = tid >> 4;
    int pt = tid & 15;
    float acc[6][4];
    #pragma unroll
    for (int i = 0; i < 6; i++)
        #pragma unroll
        for (int j = 0; j < 4; j++) acc[i][j] = 0.f;
    for (int e = 0; e < DI; e += 4){
        float4 xv[4];
        #pragma unroll
        for (int j = 0; j < 4; j++) xv[j] = *(const float4*)(syo + (pt + 16*j)*196 + e);
        #pragma unroll
        for (int i = 0; i < 6; i++){
            float4 wv = *(const float4*)(sw + (ct*6 + i)*196 + e);
            #pragma unroll
            for (int j = 0; j < 4; j++){
                acc[i][j] += wv.x*xv[j].x + wv.y*xv[j].y + wv.z*xv[j].z + wv.w*xv[j].w;
            }
        }
    }
    __syncthreads();
    #pragma unroll
    for (int i = 0; i < 6; i++)
        #pragma unroll
        for (int j = 0; j < 4; j++)
            syo[(ct*6 + i)*64 + pt + 16*j] = acc[i][j];
    __syncthreads();
    for (int idx = tid; idx < 96*64; idx += 256){
        int c = idx >> 6, jx = idx & 63;
        size_t go = ((size_t)b*96 + c)*LL + p0 + jx;
        out[go] = syo[idx] + x[go];
    }
}

// ---------------- launch ----------------
extern "C" void kernel_launch(void* const* d_in, const int* in_sizes, int n_in,
                              void* d_out, int out_size){
    const float* x    = (const float*)d_in[0];
    const float* ipw  = (const float*)d_in[1];
    const float* cw   = (const float*)d_in[2];
    const float* cb   = (const float*)d_in[3];
    const float* xpw  = (const float*)d_in[4];
    const float* dtw  = (const float*)d_in[5];
    const float* dtb  = (const float*)d_in[6];
    const float* alog = (const float*)d_in[7];
    const float* Dsv  = (const float*)d_in[8];
    const float* lng  = (const float*)d_in[9];
    const float* lnb  = (const float*)d_in[10];
    const float* opw  = (const float*)d_in[11];
    float* out = (float*)d_out;

    int smA = (128*100 + 144*100) * 4;
    int smC = (40*DI + DI*DR + DI + TLC*196 + TLC*40) * 4;
    int smE = (96*196 + 64*196 + DI + DI) * 4;
    cudaFuncSetAttribute(kA,  cudaFuncAttributeMaxDynamicSharedMemorySize, smA);
    cudaFuncSetAttribute(kC1, cudaFuncAttributeMaxDynamicSharedMemorySize, smC);
    cudaFuncSetAttribute(kE,  cudaFuncAttributeMaxDynamicSharedMemorySize, smE);

    kA<<<NB*3*64, 384, smA>>>(x, ipw);
    int nbB = (NB*(LL/2)*(DI/2) + 255)/256;
    kB<<<nbB, 256>>>(cw, cb);
    kC1<<<NB*KK*(LL/TLC), 320, smC>>>(xpw, dtw, dtb);
    kD1<<<NB*KK*NSEG, 192>>>(alog);
    kD2<<<(NB*KK*DS*DI + 255)/256, 256>>>(alog);
    kD3<<<NB*KK*NSEG, 192>>>(alog, Dsv);
    kE<<<NB*(LL/64), 256, smE>>>(opw, lng, lnb, x, out);
}